// round 4
// baseline (speedup 1.0000x reference)
#include <cuda_runtime.h>
#include <cuda_bf16.h>

#define Bsz 8
#define Tsz 2048
#define Dsz 64
#define Fsz 128

typedef unsigned long long u64;

// ---- scratch (allocation-free: __device__ globals) ----
__device__ float g_logits[Bsz * Dsz * Tsz];   // [b][d][t], 4 MB
__device__ float g_m[Bsz * Dsz];              // per-(b,d) max logit
__device__ float g_invS[Bsz * Dsz];           // per-(b,d) 1/sum(exp)
__device__ float g_c[Dsz];                    // -log_softmax(wei)
__device__ float g_dnorm[Dsz];                // ||dic_d||^2

// ---- packed f32x2 helpers (Blackwell FFMA2 path) ----
__device__ __forceinline__ u64 ffma2(u64 a, u64 b, u64 c) {
    u64 d;
    asm("fma.rn.f32x2 %0, %1, %2, %3;" : "=l"(d) : "l"(a), "l"(b), "l"(c));
    return d;
}
__device__ __forceinline__ u64 pk2(float x, float y) {
    u64 r;
    asm("mov.b64 %0, {%1, %2};" : "=l"(r) : "f"(x), "f"(y));
    return r;
}
__device__ __forceinline__ float2 upk2(u64 v) {
    float2 r;
    asm("mov.b64 {%0, %1}, %2;" : "=f"(r.x), "=f"(r.y) : "l"(v));
    return r;
}

// ============================================================
// Prep: c[d] = -(wei[d] - logsumexp(wei)),  dnorm[d] = ||dic_d||^2
// ============================================================
__global__ void k_prep(const float* __restrict__ dic, const float* __restrict__ wei) {
    __shared__ float lse_sh;
    int tid = threadIdx.x;
    if (tid < 32) {
        float a = wei[tid], b = wei[tid + 32];
        float m = fmaxf(a, b);
        #pragma unroll
        for (int off = 16; off > 0; off >>= 1)
            m = fmaxf(m, __shfl_xor_sync(0xffffffffu, m, off));
        float s = __expf(a - m) + __expf(b - m);
        #pragma unroll
        for (int off = 16; off > 0; off >>= 1)
            s += __shfl_xor_sync(0xffffffffu, s, off);
        if (tid == 0) lse_sh = m + logf(s);
    }
    __syncthreads();
    if (tid < 64) {
        g_c[tid] = -(wei[tid] - lse_sh);
        const float4* dr = (const float4*)(dic + tid * Fsz);
        float s = 0.f;
        #pragma unroll
        for (int q = 0; q < Fsz / 4; q++) {
            float4 v = dr[q];
            s += v.x * v.x + v.y * v.y + v.z * v.z + v.w * v.w;
        }
        g_dnorm[tid] = s;
    }
}

// ============================================================
// Init out = -dic (since sum_t w_soft == 1 exactly)
// ============================================================
__global__ void k_init_out(const float* __restrict__ dic, float* __restrict__ out) {
    int i = blockIdx.x * blockDim.x + threadIdx.x;  // 65536
    out[i] = -dic[i & (Dsz * Fsz - 1)];
}

// ============================================================
// K1: logits[b][d][t] = c[d] * sqrt(||x_t||^2 - 2 x.dic + ||dic_d||^2)
// tile: 64 t x 64 d, K=128. 256 thr, micro 4t x 4d, f32x2 over k.
// ============================================================
__global__ void k1_logits(const float* __restrict__ x, const float* __restrict__ dic) {
    extern __shared__ float sm[];
    float* xs   = sm;                  // [64][128]
    float* ds   = sm + 64 * 128;       // [64][130] (pad 130: conflict-free f32x2 reads)
    float* xn   = ds + 64 * 130;       // [64]
    float* dn_s = xn + 64;             // [64]
    float* c_s  = dn_s + 64;           // [64]

    int tid = threadIdx.x;
    int b = blockIdx.y;
    int t0 = blockIdx.x * 64;

    // load x tile (coalesced float4)
    {
        const float4* xg = (const float4*)(x + ((size_t)b * Tsz + t0) * Fsz);
        float4* xs4 = (float4*)xs;
        #pragma unroll
        for (int it = 0; it < 8; it++) {
            int fi = tid + it * 256;   // 2048 float4
            xs4[fi] = xg[fi];
        }
    }
    // load dic into padded smem (float2 granularity)
    {
        const float2* dg = (const float2*)dic;   // 64 rows x 64 float2
        #pragma unroll
        for (int it = 0; it < 16; it++) {
            int fi = tid + it * 256;             // 4096 float2
            int d = fi >> 6, c = fi & 63;
            *(float2*)(ds + d * 130 + c * 2) = dg[fi];
        }
    }
    if (tid < 64) { dn_s[tid] = g_dnorm[tid]; c_s[tid] = g_c[tid]; }
    __syncthreads();

    // ---- per-row ||x||^2 (rotated conflict-free reads) ----
    if (tid < 64) {
        const float4* xr = (const float4*)(xs + tid * 128);
        float s = 0.f;
        #pragma unroll
        for (int q = 0; q < 32; q++) {
            float4 v = xr[(q + tid) & 31];
            s += v.x * v.x + v.y * v.y + v.z * v.z + v.w * v.w;
        }
        xn[tid] = s;
    }
    __syncthreads();

    int tx = tid & 15, ty = tid >> 4;

    u64 acc[4][4];
    #pragma unroll
    for (int i = 0; i < 4; i++)
        #pragma unroll
        for (int j = 0; j < 4; j++) acc[i][j] = 0ull;

    const float* xbase = xs + ty * 128;   // t_i = ty + 16i
    const float* dbase = ds + tx * 130;   // d_j = tx + 16j

    #pragma unroll 4
    for (int k = 0; k < 128; k += 4) {
        u64 a0[4], a1[4], b0[4], b1[4];
        #pragma unroll
        for (int i = 0; i < 4; i++) {
            const u64* p = (const u64*)(xbase + i * 2048 + k);
            a0[i] = p[0]; a1[i] = p[1];
        }
        #pragma unroll
        for (int j = 0; j < 4; j++) {
            const u64* q = (const u64*)(dbase + j * 2080 + k);
            b0[j] = q[0]; b1[j] = q[1];
        }
        #pragma unroll
        for (int i = 0; i < 4; i++)
            #pragma unroll
            for (int j = 0; j < 4; j++) {
                acc[i][j] = ffma2(a0[i], b0[j], acc[i][j]);
                acc[i][j] = ffma2(a1[i], b1[j], acc[i][j]);
            }
    }

    float xnv[4], dnv[4], cv[4];
    #pragma unroll
    for (int i = 0; i < 4; i++) xnv[i] = xn[ty + 16 * i];
    #pragma unroll
    for (int j = 0; j < 4; j++) { int d = tx + 16 * j; dnv[j] = dn_s[d]; cv[j] = c_s[d]; }

    __syncthreads();                 // done reading xs -> reuse as staging
    float* ls = xs;                  // [64 d][68 pitch]
    #pragma unroll
    for (int i = 0; i < 4; i++)
        #pragma unroll
        for (int j = 0; j < 4; j++) {
            float2 p = upk2(acc[i][j]);
            float g = p.x + p.y;
            float d2 = fmaxf(xnv[i] - 2.f * g + dnv[j], 0.f);
            ls[(tx + 16 * j) * 68 + (ty + 16 * i)] = cv[j] * sqrtf(d2);
        }
    __syncthreads();

    // coalesced write to g_logits[b][d][t0..t0+63]
    #pragma unroll
    for (int it = 0; it < 4; it++) {
        int fi = tid + it * 256;     // 1024 float4
        int d = fi >> 4, c4 = fi & 15;
        *(float4*)(g_logits + ((size_t)(b * Dsz + d)) * Tsz + t0 + c4 * 4) =
            *(const float4*)(ls + d * 68 + c4 * 4);
    }
}

// ============================================================
// K2: per-(b,d) softmax stats over T=2048
// ============================================================
__global__ void k2_stats() {
    int bd = blockIdx.x;
    int tid = threadIdx.x;             // 256
    int lane = tid & 31, wid = tid >> 5;
    __shared__ float redm[8], reds[8];

    const float4* row = (const float4*)(g_logits + (size_t)bd * Tsz);
    float4 v1 = row[tid], v2 = row[tid + 256];

    float m = fmaxf(fmaxf(fmaxf(v1.x, v1.y), fmaxf(v1.z, v1.w)),
                    fmaxf(fmaxf(v2.x, v2.y), fmaxf(v2.z, v2.w)));
    #pragma unroll
    for (int off = 16; off > 0; off >>= 1)
        m = fmaxf(m, __shfl_xor_sync(0xffffffffu, m, off));
    if (lane == 0) redm[wid] = m;
    __syncthreads();
    float M = redm[0];
    #pragma unroll
    for (int r = 1; r < 8; r++) M = fmaxf(M, redm[r]);

    float s = __expf(v1.x - M) + __expf(v1.y - M) + __expf(v1.z - M) + __expf(v1.w - M)
            + __expf(v2.x - M) + __expf(v2.y - M) + __expf(v2.z - M) + __expf(v2.w - M);
    #pragma unroll
    for (int off = 16; off > 0; off >>= 1)
        s += __shfl_xor_sync(0xffffffffu, s, off);
    if (lane == 0) reds[wid] = s;
    __syncthreads();
    if (tid == 0) {
        float S = 0.f;
        #pragma unroll
        for (int r = 0; r < 8; r++) S += reds[r];
        g_m[bd] = M;
        g_invS[bd] = 1.f / S;
    }
}

// ============================================================
// K3: out[b][d][f] += sum_t w_soft[b,d,t] * x[b,t,f]
// tile: 64-t chunk x (64 d x 128 f). f32x2 packed over f.
// ============================================================
__global__ void k3_out(const float* __restrict__ x, float* __restrict__ out) {
    extern __shared__ float sm[];
    float* xs = sm;                 // [64 t][128 f]
    float* ws = sm + 64 * 128;      // [64 d][68 pitch over t]

    int tid = threadIdx.x;
    int b = blockIdx.y;
    int t0 = blockIdx.x * 64;

    // load x chunk
    {
        const float4* xg = (const float4*)(x + ((size_t)b * Tsz + t0) * Fsz);
        float4* xs4 = (float4*)xs;
        #pragma unroll
        for (int it = 0; it < 8; it++) {
            int fi = tid + it * 256;
            xs4[fi] = xg[fi];
        }
    }
    // compute w_soft into ws: thread -> (d = tid>>2, 16 t's)
    {
        int d = tid >> 2;
        int tq = (tid & 3) * 16;
        int bd = b * Dsz + d;
        float m = g_m[bd];
        float is = g_invS[bd];
        const float4* lr = (const float4*)(g_logits + (size_t)bd * Tsz + t0 + tq);
        float4* wr = (float4*)(ws + d * 68 + tq);
        #pragma unroll
        for (int q = 0; q < 4; q++) {
            float4 v = lr[q];
            float4 w;
            w.x = __expf(v.x - m) * is;
            w.y = __expf(v.y - m) * is;
            w.z = __expf(v.z - m) * is;
            w.w = __expf(v.w - m) * is;
            wr[q] = w;
        }
    }
    __syncthreads();

    int tx = tid & 15, ty = tid >> 4;
    u64 acc[4][4];
    #pragma unroll
    for (int i = 0; i < 4; i++)
        #pragma unroll
        for (int j = 0; j < 4; j++) acc[i][j] = 0ull;

    const float* wbase = ws + ty * 68;           // d_i = ty + 16i
    const u64* xbase = (const u64*)xs + tx;      // f-pair_j = tx + 16j

    #pragma unroll 4
    for (int t = 0; t < 64; t += 2) {
        float2 w2[4];
        #pragma unroll
        for (int i = 0; i < 4; i++)
            w2[i] = *(const float2*)(wbase + i * 16 * 68 + t);
        u64 b0[4], b1[4];
        #pragma unroll
        for (int j = 0; j < 4; j++) {
            b0[j] = xbase[t * 64 + 16 * j];
            b1[j] = xbase[(t + 1) * 64 + 16 * j];
        }
        #pragma unroll
        for (int i = 0; i < 4; i++) {
            u64 wa = pk2(w2[i].x, w2[i].x);
            u64 wb = pk2(w2[i].y, w2[i].y);
            #pragma unroll
            for (int j = 0; j < 4; j++) {
                acc[i][j] = ffma2(wa, b0[j], acc[i][j]);
                acc[i][j] = ffma2(wb, b1[j], acc[i][j]);
            }
        }
    }

    #pragma unroll
    for (int i = 0; i < 4; i++) {
        int d = ty + 16 * i;
        #pragma unroll
        for (int j = 0; j < 4; j++) {
            int f = 2 * (tx + 16 * j);
            float2 v = upk2(acc[i][j]);
            float* o = out + (size_t)b * (Dsz * Fsz) + d * Fsz + f;
            atomicAdd(o, v.x);
            atomicAdd(o + 1, v.y);
        }
    }
}

// ============================================================
extern "C" void kernel_launch(void* const* d_in, const int* in_sizes, int n_in,
                              void* d_out, int out_size) {
    const float* x   = (const float*)d_in[0];   // (8, 2048, 128)
    const float* dic = (const float*)d_in[1];   // (64, 128)
    const float* wei = (const float*)d_in[2];   // (64,)
    float* out = (float*)d_out;                 // (8, 8192)

    static bool attr_done = false;
    size_t smem1 = (64 * 128 + 64 * 130 + 64 * 3) * sizeof(float);   // 66304 B
    size_t smem3 = (64 * 128 + 64 * 68) * sizeof(float);             // 50176 B
    if (!attr_done) {
        cudaFuncSetAttribute(k1_logits, cudaFuncAttributeMaxDynamicSharedMemorySize, (int)smem1);
        cudaFuncSetAttribute(k3_out, cudaFuncAttributeMaxDynamicSharedMemorySize, (int)smem3);
        attr_done = true;
    }

    k_prep<<<1, 64>>>(dic, wei);
    k_init_out<<<(Bsz * Dsz * Fsz) / 256, 256>>>(dic, out);
    k1_logits<<<dim3(Tsz / 64, Bsz), 256, smem1>>>(x, dic);
    k2_stats<<<Bsz * Dsz, 256>>>();
    k3_out<<<dim3(Tsz / 64, Bsz), 256, smem3>>>(x, out);
}

// round 5
// speedup vs baseline: 1.0727x; 1.0727x over previous
#include <cuda_runtime.h>
#include <cuda_bf16.h>

#define Bsz 8
#define Tsz 2048
#define Dsz 64
#define Fsz 128
#define NTILE 32              // Tsz/64 tiles per (b,d) row

typedef unsigned long long u64;

// ---- scratch (allocation-free: __device__ globals) ----
__device__ float  g_logits[Bsz * Dsz * Tsz];        // [b][d][t], 4 MB
__device__ float2 g_part[Bsz * Dsz * NTILE];        // per-(b,d,tile) (max, sumexp)
__device__ float  g_c[Dsz];                         // -log_softmax(wei)
__device__ float  g_dnorm[Dsz];                     // ||dic_d||^2

// ---- packed f32x2 helpers (Blackwell FFMA2 path) ----
__device__ __forceinline__ u64 ffma2(u64 a, u64 b, u64 c) {
    u64 d;
    asm("fma.rn.f32x2 %0, %1, %2, %3;" : "=l"(d) : "l"(a), "l"(b), "l"(c));
    return d;
}
__device__ __forceinline__ u64 pk2(float x, float y) {
    u64 r;
    asm("mov.b64 %0, {%1, %2};" : "=l"(r) : "f"(x), "f"(y));
    return r;
}
__device__ __forceinline__ float2 upk2(u64 v) {
    float2 r;
    asm("mov.b64 {%0, %1}, %2;" : "=f"(r.x), "=f"(r.y) : "l"(v));
    return r;
}

// ============================================================
// Prep + out-init fused.
// grid 32 x 256: all blocks init out = -dic (sum_t w_soft == 1 exactly).
// block 0 additionally computes c[d], dnorm[d].
// ============================================================
__global__ void k_prep_init(const float* __restrict__ dic,
                            const float* __restrict__ wei,
                            float* __restrict__ out) {
    int i = blockIdx.x * 256 + threadIdx.x;        // 0..8191
    float v = -dic[i];
    #pragma unroll
    for (int r = 0; r < Bsz; r++) out[i + r * (Dsz * Fsz)] = v;

    if (blockIdx.x == 0) {
        __shared__ float lse_sh;
        int tid = threadIdx.x;
        if (tid < 32) {
            float a = wei[tid], b = wei[tid + 32];
            float m = fmaxf(a, b);
            #pragma unroll
            for (int off = 16; off > 0; off >>= 1)
                m = fmaxf(m, __shfl_xor_sync(0xffffffffu, m, off));
            float s = __expf(a - m) + __expf(b - m);
            #pragma unroll
            for (int off = 16; off > 0; off >>= 1)
                s += __shfl_xor_sync(0xffffffffu, s, off);
            if (tid == 0) lse_sh = m + logf(s);
        }
        __syncthreads();
        if (tid < 64) {
            g_c[tid] = -(wei[tid] - lse_sh);
            const float4* dr = (const float4*)(dic + tid * Fsz);
            float s = 0.f;
            #pragma unroll
            for (int q = 0; q < Fsz / 4; q++) {
                float4 v4 = dr[q];
                s += v4.x * v4.x + v4.y * v4.y + v4.z * v4.z + v4.w * v4.w;
            }
            g_dnorm[tid] = s;
        }
    }
}

// ============================================================
// K1: logits[b][d][t] = c[d] * sqrt(||x_t||^2 - 2 x.dic + ||dic_d||^2)
// tile 64t x 64d, K=128, 256 thr, micro 4x4, f32x2.
// Epilogue also emits per-tile softmax partials (m, sumexp).
// ============================================================
__global__ void k1_logits(const float* __restrict__ x, const float* __restrict__ dic) {
    extern __shared__ float sm[];
    float* xs   = sm;                  // [64][128]
    float* ds   = sm + 64 * 128;       // [64][130]
    float* xn   = ds + 64 * 130;       // [64]
    float* dn_s = xn + 64;             // [64]
    float* c_s  = dn_s + 64;           // [64]

    int tid = threadIdx.x;
    int b = blockIdx.y;
    int tile = blockIdx.x;
    int t0 = tile * 64;

    {
        const float4* xg = (const float4*)(x + ((size_t)b * Tsz + t0) * Fsz);
        float4* xs4 = (float4*)xs;
        #pragma unroll
        for (int it = 0; it < 8; it++) {
            int fi = tid + it * 256;
            xs4[fi] = xg[fi];
        }
    }
    {
        const float2* dg = (const float2*)dic;   // 64 rows x 64 float2
        #pragma unroll
        for (int it = 0; it < 16; it++) {
            int fi = tid + it * 256;
            int d = fi >> 6, c = fi & 63;
            *(float2*)(ds + d * 130 + c * 2) = dg[fi];
        }
    }
    if (tid < 64) { dn_s[tid] = g_dnorm[tid]; c_s[tid] = g_c[tid]; }
    __syncthreads();

    if (tid < 64) {
        const float4* xr = (const float4*)(xs + tid * 128);
        float s = 0.f;
        #pragma unroll
        for (int q = 0; q < 32; q++) {
            float4 v = xr[(q + tid) & 31];
            s += v.x * v.x + v.y * v.y + v.z * v.z + v.w * v.w;
        }
        xn[tid] = s;
    }
    __syncthreads();

    int tx = tid & 15, ty = tid >> 4;

    u64 acc[4][4];
    #pragma unroll
    for (int i = 0; i < 4; i++)
        #pragma unroll
        for (int j = 0; j < 4; j++) acc[i][j] = 0ull;

    const float* xbase = xs + ty * 128;
    const float* dbase = ds + tx * 130;

    #pragma unroll 4
    for (int k = 0; k < 128; k += 4) {
        u64 a0[4], a1[4], b0[4], b1[4];
        #pragma unroll
        for (int i = 0; i < 4; i++) {
            const u64* p = (const u64*)(xbase + i * 2048 + k);
            a0[i] = p[0]; a1[i] = p[1];
        }
        #pragma unroll
        for (int j = 0; j < 4; j++) {
            const u64* q = (const u64*)(dbase + j * 2080 + k);
            b0[j] = q[0]; b1[j] = q[1];
        }
        #pragma unroll
        for (int i = 0; i < 4; i++)
            #pragma unroll
            for (int j = 0; j < 4; j++) {
                acc[i][j] = ffma2(a0[i], b0[j], acc[i][j]);
                acc[i][j] = ffma2(a1[i], b1[j], acc[i][j]);
            }
    }

    float xnv[4], dnv[4], cv[4];
    #pragma unroll
    for (int i = 0; i < 4; i++) xnv[i] = xn[ty + 16 * i];
    #pragma unroll
    for (int j = 0; j < 4; j++) { int d = tx + 16 * j; dnv[j] = dn_s[d]; cv[j] = c_s[d]; }

    __syncthreads();
    float* ls = xs;                 // [64 d][68]
    #pragma unroll
    for (int i = 0; i < 4; i++)
        #pragma unroll
        for (int j = 0; j < 4; j++) {
            float2 p = upk2(acc[i][j]);
            float g = p.x + p.y;
            float d2 = fmaxf(xnv[i] - 2.f * g + dnv[j], 0.f);
            ls[(tx + 16 * j) * 68 + (ty + 16 * i)] = cv[j] * sqrtf(d2);
        }
    __syncthreads();

    // coalesced write of logits
    #pragma unroll
    for (int it = 0; it < 4; it++) {
        int fi = tid + it * 256;
        int d = fi >> 4, c4 = fi & 15;
        *(float4*)(g_logits + ((size_t)(b * Dsz + d)) * Tsz + t0 + c4 * 4) =
            *(const float4*)(ls + d * 68 + c4 * 4);
    }

    // per-tile softmax partials: 4 threads per d, 16 t each
    {
        int d = tid >> 2;
        int tq = (tid & 3) * 16;
        const float* lp = ls + d * 68 + tq;
        float m = -3.4e38f;
        #pragma unroll
        for (int q = 0; q < 16; q++) m = fmaxf(m, lp[q]);
        float s = 0.f;
        #pragma unroll
        for (int q = 0; q < 16; q++) s += __expf(lp[q] - m);
        #pragma unroll
        for (int off = 1; off < 4; off <<= 1) {
            float mo = __shfl_xor_sync(0xffffffffu, m, off);
            float so = __shfl_xor_sync(0xffffffffu, s, off);
            float M = fmaxf(m, mo);
            s = s * __expf(m - M) + so * __expf(mo - M);
            m = M;
        }
        if ((tid & 3) == 0)
            g_part[(b * Dsz + d) * NTILE + tile] = make_float2(m, s);
    }
}

// ============================================================
// K3: out[b][d][f] += sum_t w[b,d,t] * x[b,t,f]
// grid (16, 8): 128-t chunk per block (2 sub-tiles of 64, persistent acc).
// Prologue combines softmax partials for this b (redundant per block, cheap).
// ============================================================
__global__ void k3_out(const float* __restrict__ x, float* __restrict__ out) {
    extern __shared__ float sm[];
    float*  xs = sm;                 // [64 t][128 f]
    float*  ws = sm + 64 * 128;      // [64 d][68 pitch over t]
    float2* mS = (float2*)(ws + 64 * 68);  // [64] (M, invS)

    int tid = threadIdx.x;
    int b = blockIdx.y;
    int t00 = blockIdx.x * 128;

    // combine per-tile partials -> (M, 1/S) for each d of this b
    if (tid < 64) {
        const float2* pp = &g_part[(b * Dsz + tid) * NTILE];
        float2 p[NTILE];
        #pragma unroll
        for (int q = 0; q < NTILE; q++) p[q] = pp[q];
        float M = p[0].x;
        #pragma unroll
        for (int q = 1; q < NTILE; q++) M = fmaxf(M, p[q].x);
        float S = 0.f;
        #pragma unroll
        for (int q = 0; q < NTILE; q++) S += p[q].y * __expf(p[q].x - M);
        mS[tid] = make_float2(M, 1.f / S);
    }
    __syncthreads();

    int dw = tid >> 2;
    float2 msv = mS[dw];
    int tx = tid & 15, ty = tid >> 4;

    u64 acc[4][4];
    #pragma unroll
    for (int i = 0; i < 4; i++)
        #pragma unroll
        for (int j = 0; j < 4; j++) acc[i][j] = 0ull;

    #pragma unroll
    for (int sub = 0; sub < 2; sub++) {
        int t0 = t00 + sub * 64;
        if (sub) __syncthreads();    // xs/ws reuse

        {
            const float4* xg = (const float4*)(x + ((size_t)b * Tsz + t0) * Fsz);
            float4* xs4 = (float4*)xs;
            #pragma unroll
            for (int it = 0; it < 8; it++) {
                int fi = tid + it * 256;
                xs4[fi] = xg[fi];
            }
        }
        {
            int tq = (tid & 3) * 16;
            const float4* lr = (const float4*)(g_logits + (size_t)(b * Dsz + dw) * Tsz + t0 + tq);
            float4* wr = (float4*)(ws + dw * 68 + tq);
            #pragma unroll
            for (int q = 0; q < 4; q++) {
                float4 v = lr[q];
                float4 w;
                w.x = __expf(v.x - msv.x) * msv.y;
                w.y = __expf(v.y - msv.x) * msv.y;
                w.z = __expf(v.z - msv.x) * msv.y;
                w.w = __expf(v.w - msv.x) * msv.y;
                wr[q] = w;
            }
        }
        __syncthreads();

        const float* wbase = ws + ty * 68;
        const u64* xbase = (const u64*)xs + tx;

        #pragma unroll 4
        for (int t = 0; t < 64; t += 2) {
            float2 w2[4];
            #pragma unroll
            for (int i = 0; i < 4; i++)
                w2[i] = *(const float2*)(wbase + i * 16 * 68 + t);
            u64 b0[4], b1[4];
            #pragma unroll
            for (int j = 0; j < 4; j++) {
                b0[j] = xbase[t * 64 + 16 * j];
                b1[j] = xbase[(t + 1) * 64 + 16 * j];
            }
            #pragma unroll
            for (int i = 0; i < 4; i++) {
                u64 wa = pk2(w2[i].x, w2[i].x);
                u64 wb = pk2(w2[i].y, w2[i].y);
                #pragma unroll
                for (int j = 0; j < 4; j++) {
                    acc[i][j] = ffma2(wa, b0[j], acc[i][j]);
                    acc[i][j] = ffma2(wb, b1[j], acc[i][j]);
                }
            }
        }
    }

    #pragma unroll
    for (int i = 0; i < 4; i++) {
        int d = ty + 16 * i;
        #pragma unroll
        for (int j = 0; j < 4; j++) {
            int f = 2 * (tx + 16 * j);
            float2 v = upk2(acc[i][j]);
            float* o = out + (size_t)b * (Dsz * Fsz) + d * Fsz + f;
            atomicAdd(o, v.x);
            atomicAdd(o + 1, v.y);
        }
    }
}

// ============================================================
extern "C" void kernel_launch(void* const* d_in, const int* in_sizes, int n_in,
                              void* d_out, int out_size) {
    const float* x   = (const float*)d_in[0];   // (8, 2048, 128)
    const float* dic = (const float*)d_in[1];   // (64, 128)
    const float* wei = (const float*)d_in[2];   // (64,)
    float* out = (float*)d_out;                 // (8, 8192)

    size_t smem1 = (64 * 128 + 64 * 130 + 64 * 3) * sizeof(float);         // 66816 B
    size_t smem3 = (64 * 128 + 64 * 68 + 128) * sizeof(float);             // 50688 B
    cudaFuncSetAttribute(k1_logits, cudaFuncAttributeMaxDynamicSharedMemorySize, (int)smem1);
    cudaFuncSetAttribute(k3_out, cudaFuncAttributeMaxDynamicSharedMemorySize, (int)smem3);

    k_prep_init<<<32, 256>>>(dic, wei, out);
    k1_logits<<<dim3(NTILE, Bsz), 256, smem1>>>(x, dic);
    k3_out<<<dim3(Tsz / 128, Bsz), 256, smem3>>>(x, out);
}

// round 6
// speedup vs baseline: 1.1493x; 1.0714x over previous
#include <cuda_runtime.h>
#include <cuda_bf16.h>

#define Bsz 8
#define Tsz 2048
#define Dsz 64
#define Fsz 128
#define NTILE 32              // Tsz/64 tiles per (b,d) row

typedef unsigned long long u64;

// ---- scratch (allocation-free: __device__ globals) ----
__device__ float  g_logits[Bsz * Dsz * Tsz];        // [b][d][t], 4 MB
__device__ float2 g_part[Bsz * Dsz * NTILE];        // per-(b,d,tile) (max, sumexp)

// ---- packed f32x2 helpers (Blackwell FFMA2 path) ----
__device__ __forceinline__ u64 ffma2(u64 a, u64 b, u64 c) {
    u64 d;
    asm("fma.rn.f32x2 %0, %1, %2, %3;" : "=l"(d) : "l"(a), "l"(b), "l"(c));
    return d;
}
__device__ __forceinline__ u64 pk2(float x, float y) {
    u64 r;
    asm("mov.b64 %0, {%1, %2};" : "=l"(r) : "f"(x), "f"(y));
    return r;
}
__device__ __forceinline__ float2 upk2(u64 v) {
    float2 r;
    asm("mov.b64 {%0, %1}, %2;" : "=f"(r.x), "=f"(r.y) : "l"(v));
    return r;
}

// ============================================================
// K1: logits[b][d][t] = c[d] * sqrt(||x_t||^2 - 2 x.dic + ||dic_d||^2)
// tile 64t x 64d, K=128, 256 thr, micro 4x4, f32x2.
// Self-contained: computes c[d] (from wei) and ||dic_d||^2 (from smem dic)
// per block; tile==0 blocks also init out = -dic (sum_t w == 1 exactly).
// Epilogue emits per-tile softmax partials (m, sumexp).
// ============================================================
__global__ void k1_logits(const float* __restrict__ x, const float* __restrict__ dic,
                          const float* __restrict__ wei, float* __restrict__ out) {
    extern __shared__ float sm[];
    float* xs   = sm;                  // [64][128]
    float* ds   = sm + 64 * 128;       // [64][130]
    float* xn   = ds + 64 * 130;       // [64]
    float* dn_s = xn + 64;             // [64]
    float* c_s  = dn_s + 64;           // [64]
    float* lse_sh = c_s + 64;          // [1]

    int tid = threadIdx.x;
    int b = blockIdx.y;
    int tile = blockIdx.x;
    int t0 = tile * 64;

    // load x tile (coalesced float4)
    {
        const float4* xg = (const float4*)(x + ((size_t)b * Tsz + t0) * Fsz);
        float4* xs4 = (float4*)xs;
        #pragma unroll
        for (int it = 0; it < 8; it++) {
            int fi = tid + it * 256;
            xs4[fi] = xg[fi];
        }
    }
    // load dic into padded smem
    {
        const float2* dg = (const float2*)dic;   // 64 rows x 64 float2
        #pragma unroll
        for (int it = 0; it < 16; it++) {
            int fi = tid + it * 256;
            int d = fi >> 6, c = fi & 63;
            *(float2*)(ds + d * 130 + c * 2) = dg[fi];
        }
    }
    // lse(wei) on warp 7 (no smem deps)
    if ((tid >> 5) == 7) {
        int lane = tid & 31;
        float a = wei[lane], bb = wei[lane + 32];
        float m = fmaxf(a, bb);
        #pragma unroll
        for (int off = 16; off > 0; off >>= 1)
            m = fmaxf(m, __shfl_xor_sync(0xffffffffu, m, off));
        float s = __expf(a - m) + __expf(bb - m);
        #pragma unroll
        for (int off = 16; off > 0; off >>= 1)
            s += __shfl_xor_sync(0xffffffffu, s, off);
        if (lane == 0) *lse_sh = m + logf(s);
    }
    // out init from tile==0 blocks (ordered before k3 atomics by launch order)
    if (tile == 0) {
        const float4* dg4 = (const float4*)dic;
        float4* og4 = (float4*)(out + (size_t)b * (Dsz * Fsz));
        #pragma unroll
        for (int it = 0; it < 8; it++) {
            int fi = tid + it * 256;           // 2048 float4
            float4 v = dg4[fi];
            og4[fi] = make_float4(-v.x, -v.y, -v.z, -v.w);
        }
    }
    __syncthreads();

    // per-row ||x||^2 (threads 0-63) and ||dic||^2 (threads 64-127), parallel
    if (tid < 64) {
        const float4* xr = (const float4*)(xs + tid * 128);
        float s = 0.f;
        #pragma unroll
        for (int q = 0; q < 32; q++) {
            float4 v = xr[(q + tid) & 31];
            s += v.x * v.x + v.y * v.y + v.z * v.z + v.w * v.w;
        }
        xn[tid] = s;
    } else if (tid < 128) {
        int d = tid - 64;
        const float2* drow = (const float2*)(ds + d * 130);
        float s = 0.f;
        #pragma unroll
        for (int q = 0; q < 64; q++) {
            float2 v = drow[(q + d) & 63];
            s += v.x * v.x + v.y * v.y;
        }
        dn_s[d] = s;
    } else if (tid < 192) {
        int d = tid - 128;
        c_s[d] = -(wei[d] - *lse_sh);
    }
    __syncthreads();

    int tx = tid & 15, ty = tid >> 4;

    u64 acc[4][4];
    #pragma unroll
    for (int i = 0; i < 4; i++)
        #pragma unroll
        for (int j = 0; j < 4; j++) acc[i][j] = 0ull;

    const float* xbase = xs + ty * 128;   // t_i = ty + 16i
    const float* dbase = ds + tx * 130;   // d_j = tx + 16j

    #pragma unroll 4
    for (int k = 0; k < 128; k += 4) {
        u64 a0[4], a1[4], b0[4], b1[4];
        #pragma unroll
        for (int i = 0; i < 4; i++) {
            const u64* p = (const u64*)(xbase + i * 2048 + k);
            a0[i] = p[0]; a1[i] = p[1];
        }
        #pragma unroll
        for (int j = 0; j < 4; j++) {
            const u64* q = (const u64*)(dbase + j * 2080 + k);
            b0[j] = q[0]; b1[j] = q[1];
        }
        #pragma unroll
        for (int i = 0; i < 4; i++)
            #pragma unroll
            for (int j = 0; j < 4; j++) {
                acc[i][j] = ffma2(a0[i], b0[j], acc[i][j]);
                acc[i][j] = ffma2(a1[i], b1[j], acc[i][j]);
            }
    }

    float xnv[4], dnv[4], cv[4];
    #pragma unroll
    for (int i = 0; i < 4; i++) xnv[i] = xn[ty + 16 * i];
    #pragma unroll
    for (int j = 0; j < 4; j++) { int d = tx + 16 * j; dnv[j] = dn_s[d]; cv[j] = c_s[d]; }

    __syncthreads();                 // done reading xs -> reuse as staging
    float* ls = xs;                  // [64 d][68]
    #pragma unroll
    for (int i = 0; i < 4; i++)
        #pragma unroll
        for (int j = 0; j < 4; j++) {
            float2 p = upk2(acc[i][j]);
            float g = p.x + p.y;
            float d2 = fmaxf(xnv[i] - 2.f * g + dnv[j], 0.f);
            ls[(tx + 16 * j) * 68 + (ty + 16 * i)] = cv[j] * sqrtf(d2);
        }
    __syncthreads();

    // coalesced write of logits
    #pragma unroll
    for (int it = 0; it < 4; it++) {
        int fi = tid + it * 256;
        int d = fi >> 4, c4 = fi & 15;
        *(float4*)(g_logits + ((size_t)(b * Dsz + d)) * Tsz + t0 + c4 * 4) =
            *(const float4*)(ls + d * 68 + c4 * 4);
    }

    // per-tile softmax partials: 4 threads per d, 16 t each
    {
        int d = tid >> 2;
        int tq = (tid & 3) * 16;
        const float* lp = ls + d * 68 + tq;
        float m = -3.4e38f;
        #pragma unroll
        for (int q = 0; q < 16; q++) m = fmaxf(m, lp[q]);
        float s = 0.f;
        #pragma unroll
        for (int q = 0; q < 16; q++) s += __expf(lp[q] - m);
        #pragma unroll
        for (int off = 1; off < 4; off <<= 1) {
            float mo = __shfl_xor_sync(0xffffffffu, m, off);
            float so = __shfl_xor_sync(0xffffffffu, s, off);
            float M = fmaxf(m, mo);
            s = s * __expf(m - M) + so * __expf(mo - M);
            m = M;
        }
        if ((tid & 3) == 0)
            g_part[(b * Dsz + d) * NTILE + tile] = make_float2(m, s);
    }
}

// ============================================================
// K3: out[b][d][f] += sum_t w[b,d,t] * x[b,t,f]
// grid (16, 8): 128-t chunk per block, persistent accumulators.
// Prologue combines softmax partials for this b.
// ============================================================
__global__ void k3_out(const float* __restrict__ x, float* __restrict__ out) {
    extern __shared__ float sm[];
    float*  xs = sm;                 // [64 t][128 f]
    float*  ws = sm + 64 * 128;      // [64 d][68 pitch over t]
    float2* mS = (float2*)(ws + 64 * 68);  // [64] (M, invS)

    int tid = threadIdx.x;
    int b = blockIdx.y;
    int t00 = blockIdx.x * 128;

    // combine per-tile partials -> (M, 1/S) per d
    if (tid < 64) {
        const float2* pp = &g_part[(b * Dsz + tid) * NTILE];
        float2 p[NTILE];
        #pragma unroll
        for (int q = 0; q < NTILE; q++) p[q] = pp[q];
        float M = p[0].x;
        #pragma unroll
        for (int q = 1; q < NTILE; q++) M = fmaxf(M, p[q].x);
        float S = 0.f;
        #pragma unroll
        for (int q = 0; q < NTILE; q++) S += p[q].y * __expf(p[q].x - M);
        mS[tid] = make_float2(M, 1.f / S);
    }
    __syncthreads();

    int dw = tid >> 2;
    float2 msv = mS[dw];
    int tx = tid & 15, ty = tid >> 4;

    u64 acc[4][4];
    #pragma unroll
    for (int i = 0; i < 4; i++)
        #pragma unroll
        for (int j = 0; j < 4; j++) acc[i][j] = 0ull;

    #pragma unroll
    for (int sub = 0; sub < 2; sub++) {
        int t0 = t00 + sub * 64;
        if (sub) __syncthreads();

        {
            const float4* xg = (const float4*)(x + ((size_t)b * Tsz + t0) * Fsz);
            float4* xs4 = (float4*)xs;
            #pragma unroll
            for (int it = 0; it < 8; it++) {
                int fi = tid + it * 256;
                xs4[fi] = xg[fi];
            }
        }
        {
            int tq = (tid & 3) * 16;
            const float4* lr = (const float4*)(g_logits + (size_t)(b * Dsz + dw) * Tsz + t0 + tq);
            float4* wr = (float4*)(ws + dw * 68 + tq);
            #pragma unroll
            for (int q = 0; q < 4; q++) {
                float4 v = lr[q];
                float4 w;
                w.x = __expf(v.x - msv.x) * msv.y;
                w.y = __expf(v.y - msv.x) * msv.y;
                w.z = __expf(v.z - msv.x) * msv.y;
                w.w = __expf(v.w - msv.x) * msv.y;
                wr[q] = w;
            }
        }
        __syncthreads();

        const float* wbase = ws + ty * 68;
        const u64* xbase = (const u64*)xs + tx;

        #pragma unroll 4
        for (int t = 0; t < 64; t += 2) {
            float2 w2[4];
            #pragma unroll
            for (int i = 0; i < 4; i++)
                w2[i] = *(const float2*)(wbase + i * 16 * 68 + t);
            u64 b0[4], b1[4];
            #pragma unroll
            for (int j = 0; j < 4; j++) {
                b0[j] = xbase[t * 64 + 16 * j];
                b1[j] = xbase[(t + 1) * 64 + 16 * j];
            }
            #pragma unroll
            for (int i = 0; i < 4; i++) {
                u64 wa = pk2(w2[i].x, w2[i].x);
                u64 wb = pk2(w2[i].y, w2[i].y);
                #pragma unroll
                for (int j = 0; j < 4; j++) {
                    acc[i][j] = ffma2(wa, b0[j], acc[i][j]);
                    acc[i][j] = ffma2(wb, b1[j], acc[i][j]);
                }
            }
        }
    }

    #pragma unroll
    for (int i = 0; i < 4; i++) {
        int d = ty + 16 * i;
        #pragma unroll
        for (int j = 0; j < 4; j++) {
            int f = 2 * (tx + 16 * j);
            float2 v = upk2(acc[i][j]);
            float* o = out + (size_t)b * (Dsz * Fsz) + d * Fsz + f;
            atomicAdd(o, v.x);
            atomicAdd(o + 1, v.y);
        }
    }
}

// ============================================================
extern "C" void kernel_launch(void* const* d_in, const int* in_sizes, int n_in,
                              void* d_out, int out_size) {
    const float* x   = (const float*)d_in[0];   // (8, 2048, 128)
    const float* dic = (const float*)d_in[1];   // (64, 128)
    const float* wei = (const float*)d_in[2];   // (64,)
    float* out = (float*)d_out;                 // (8, 8192)

    size_t smem1 = (64 * 128 + 64 * 130 + 64 * 3 + 4) * sizeof(float);     // ~66832 B
    size_t smem3 = (64 * 128 + 64 * 68 + 128) * sizeof(float);             // 50688 B
    cudaFuncSetAttribute(k1_logits, cudaFuncAttributeMaxDynamicSharedMemorySize, (int)smem1);
    cudaFuncSetAttribute(k3_out, cudaFuncAttributeMaxDynamicSharedMemorySize, (int)smem3);

    k1_logits<<<dim3(NTILE, Bsz), 256, smem1>>>(x, dic, wei, out);
    k3_out<<<dim3(Tsz / 128, Bsz), 256, smem3>>>(x, out);
}